// round 14
// baseline (speedup 1.0000x reference)
#include <cuda_runtime.h>
#include <cuda_bf16.h>
#include <cuda_fp16.h>
#include <cstdint>
#include <math.h>

#define BB 8
#define CC_ 128
#define HH 64
#define WW 64
#define NPH 32
#define NP 1024

typedef unsigned long long u64;

// ---------------- scratch (device globals; no allocs allowed) ----------------
__device__ __nv_bfloat16 d_xhi[16 * NP * CC_];          // [z][n][c] 4 MB
__device__ __nv_bfloat16 d_xlo[16 * NP * CC_];          // [z][n][c] 4 MB
__device__ __half d_E[(size_t)16 * NP * NP];            // [z][n][m] E=exp(a*f) 32 MB
__device__ float d_w[BB * 3 * NP];                      // [b][ch][n]: w0,w1,i2

// ---------------- helpers ----------------
__device__ __forceinline__ uint32_t smem_to_u32(const void* p) {
    uint32_t a;
    asm("{ .reg .u64 t; cvta.to.shared.u64 t, %1; cvt.u32.u64 %0, t; }"
        : "=r"(a) : "l"(p));
    return a;
}
__device__ __forceinline__ float sqrta(float x) {
    float r; asm("sqrt.approx.f32 %0, %1;" : "=f"(r) : "f"(x)); return r;
}
__device__ __forceinline__ float rsqrta(float x) {
    float r; asm("rsqrt.approx.f32 %0, %1;" : "=f"(r) : "f"(x)); return r;
}
#define LDSM_X4(r, addr) \
    asm volatile("ldmatrix.sync.aligned.m8n8.x4.shared.b16 {%0,%1,%2,%3}, [%4];" \
        : "=r"((r)[0]), "=r"((r)[1]), "=r"((r)[2]), "=r"((r)[3]) : "r"(addr))
#define MMA16816(c, a, b) \
    asm volatile("mma.sync.aligned.m16n8k16.row.col.f32.bf16.bf16.f32 " \
        "{%0,%1,%2,%3}, {%4,%5,%6,%7}, {%8,%9}, {%0,%1,%2,%3};" \
        : "+f"((c)[0]), "+f"((c)[1]), "+f"((c)[2]), "+f"((c)[3]) \
        : "r"((a)[0]), "r"((a)[1]), "r"((a)[2]), "r"((a)[3]), \
          "r"((b)[0]), "r"((b)[1]))

// swizzled smem byte offset for bf16 tile [128 rows][8 x 16B chunks] (128B rows)
__device__ __forceinline__ uint32_t sw64(int row, int c16) {
    return (uint32_t)((row << 7) | (((c16) ^ (row & 7)) << 4));
}

// ================= K1: L2-normalize over C, extract diag pixels, bf16 split =
// block = (b, h, w-half): 128c x 32w tile; writes 16 patch columns (one plane).
__global__ void __launch_bounds__(128) k1_norm(const float* __restrict__ x) {
    __shared__ float xs[CC_][33];
    __shared__ float ssp[4][32];
    __shared__ float invn[32];
    int b = blockIdx.y;
    int hw = blockIdx.x;                 // 0..127
    int h = hw >> 1, half = hw & 1;
    int tid = threadIdx.x;
    const float* xrow = x + ((size_t)b * CC_ * HH + h) * WW + half * 32;
    for (int idx = tid; idx < CC_ * 32; idx += 128) {
        int c = idx >> 5, w = idx & 31;
        xs[c][w] = xrow[(size_t)c * HH * WW + w];
    }
    __syncthreads();
    {
        int w = tid & 31, c4 = tid >> 5;
        float ss = 0.f;
        #pragma unroll 8
        for (int c = c4 * 32; c < c4 * 32 + 32; c++) {
            float v = xs[c][w];
            ss += v * v;
        }
        ssp[c4][w] = ss;
    }
    __syncthreads();
    if (tid < 32) {
        float s = ssp[0][tid] + ssp[1][tid] + ssp[2][tid] + ssp[3][tid];
        invn[tid] = 1.0f / fmaxf(sqrtf(s), 1e-12f);
    }
    __syncthreads();
    int p = h & 1;
    int z = b * 2 + p;
    int nb = (h >> 1) * NPH + half * 16;
    for (int idx = tid; idx < 16 * CC_; idx += 128) {
        int j16 = idx >> 7, c = idx & 127;
        int wl = 2 * j16 + p;            // local w within the 32-col window
        float v = xs[c][wl] * invn[wl];
        __nv_bfloat16 hi = __float2bfloat16(v);
        float lo = v - __bfloat162float(hi);
        size_t o = ((size_t)z * NP + nb + j16) * CC_ + c;
        d_xhi[o] = hi;
        d_xlo[o] = __float2bfloat16(lo);
    }
}

// ================= K2: bf16 split Gram GEMM + fused exp(mask) epilogue ======
// E[z][n][m] = exp(corr * alpha*(1-mask)); triangle tiles, fp16 store (norm+T).
#define OP_AHI 0
#define OP_ALO 16384
#define OP_BHI 32768
#define OP_BLO 49152
#define STG_LD 129
#define ER_OFF 66048
#define K2_SMEM 66304

__global__ void __launch_bounds__(256, 2) k2_gemm(const float* __restrict__ alphap) {
    extern __shared__ char sm[];
    uint32_t smem_base = smem_to_u32(sm);
    int tid = threadIdx.x;
    int wid = tid >> 5, lane = tid & 31;
    int wm = wid & 3, wn = wid >> 2;
    float* er = (float*)(sm + ER_OFF);
    if (tid < 32) er[tid] = expf(-(float)(tid * tid) / 5.12f);

    // triangle tile decode
    int u = blockIdx.x, ti = 0;
    for (;;) { int row = 8 - ti; if (u < row) break; u -= row; ti++; }
    int tj = ti + u;
    int n0 = ti * 128, m0 = tj * 128;
    int z = blockIdx.y;

    const __nv_bfloat16* xh = d_xhi + (size_t)z * NP * CC_;
    const __nv_bfloat16* xl = d_xlo + (size_t)z * NP * CC_;

    float acc[2][8][4];
    #pragma unroll
    for (int i = 0; i < 2; i++)
        #pragma unroll
        for (int j = 0; j < 8; j++)
            #pragma unroll
            for (int q = 0; q < 4; q++) acc[i][j][q] = 0.f;

    int a_row_lo = (lane & 15), a_half = lane >> 4;
    int b_row_lo = (lane & 7) + ((lane >> 4) << 3);
    int b_half = (lane >> 3) & 1;

    for (int kk = 0; kk < CC_; kk += 64) {
        // load 4 operand tiles [128 x 64] bf16 each
        for (int idx = tid; idx < 1024; idx += 256) {
            int row = idx >> 3, c16 = idx & 7;
            uint32_t off = sw64(row, c16);
            size_t ga = (size_t)(n0 + row) * CC_ + kk + c16 * 8;
            size_t gb = (size_t)(m0 + row) * CC_ + kk + c16 * 8;
            *(uint4*)(sm + OP_AHI + off) = *(const uint4*)(xh + ga);
            *(uint4*)(sm + OP_ALO + off) = *(const uint4*)(xl + ga);
            *(uint4*)(sm + OP_BHI + off) = *(const uint4*)(xh + gb);
            *(uint4*)(sm + OP_BLO + off) = *(const uint4*)(xl + gb);
        }
        __syncthreads();
        const uint32_t aoff[3] = { OP_AHI, OP_AHI, OP_ALO };
        const uint32_t boff[3] = { OP_BHI, OP_BLO, OP_BHI };
        #pragma unroll
        for (int t = 0; t < 3; t++) {
            uint32_t abase = smem_base + aoff[t];
            uint32_t bbase = smem_base + boff[t];
            #pragma unroll
            for (int kc = 0; kc < 4; kc++) {
                uint32_t a[2][4];
                #pragma unroll
                for (int mi = 0; mi < 2; mi++) {
                    int row = wm * 32 + mi * 16 + a_row_lo;
                    LDSM_X4(a[mi], abase + sw64(row, 2 * kc + a_half));
                }
                uint32_t bf[4][4];
                #pragma unroll
                for (int ni16 = 0; ni16 < 4; ni16++) {
                    int row = wn * 64 + ni16 * 16 + b_row_lo;
                    LDSM_X4(bf[ni16], bbase + sw64(row, 2 * kc + b_half));
                }
                #pragma unroll
                for (int mi = 0; mi < 2; mi++)
                    #pragma unroll
                    for (int ni = 0; ni < 8; ni++)
                        MMA16816(acc[mi][ni], a[mi], (&bf[ni >> 1][(ni & 1) * 2]));
            }
        }
        __syncthreads();
    }

    // epilogue: E = exp(v * alpha*(1-mask)) into fp32 stage (LD=129)
    float alpha = __ldg(alphap);
    float* stage = (float*)sm;
    int r_base = wm * 32 + (lane >> 2);
    int c_base = wn * 64 + 2 * (lane & 3);
    #pragma unroll
    for (int mi = 0; mi < 2; mi++)
        #pragma unroll
        for (int ni = 0; ni < 8; ni++)
            #pragma unroll
            for (int q = 0; q < 4; q++) {
                int r = r_base + mi * 16 + (q >> 1) * 8;
                int c = c_base + ni * 8 + (q & 1);
                int n = n0 + r, m = m0 + c;
                float g = er[abs((n >> 5) - (m >> 5))] * er[abs((n & 31) - (m & 31))];
                stage[r * STG_LD + c] = __expf(acc[mi][ni][q] * (alpha * (1.0f - g)));
            }
    __syncthreads();

    __half* Ez = d_E + (size_t)z * NP * NP;
    // normal store (half2)
    for (int idx = tid; idx < 128 * 64; idx += 256) {
        int row = idx >> 6, c2 = (idx & 63) * 2;
        float a = stage[row * STG_LD + c2];
        float c = stage[row * STG_LD + c2 + 1];
        __half2 h = __floats2half2_rn(a, c);
        *(__half2*)(Ez + (size_t)(n0 + row) * NP + m0 + c2) = h;
    }
    // transposed store for off-diagonal tiles (half2)
    if (ti != tj) {
        for (int idx = tid; idx < 128 * 64; idx += 256) {
            int mrow = idx >> 6, nc = (idx & 63) * 2;
            float a = stage[nc * STG_LD + mrow];
            float c = stage[(nc + 1) * STG_LD + mrow];
            __half2 h = __floats2half2_rn(a, c);
            *(__half2*)(Ez + (size_t)(m0 + mrow) * NP + n0 + nc) = h;
        }
    }
}

// ================= K3: row sums of E (fp16); 1 warp = 1 row; store w0,w1,i2 =
__global__ void __launch_bounds__(128) k3_rowsum() {
    int tid = threadIdx.x, wid = tid >> 5, lane = tid & 31;
    int blk = blockIdx.x;            // 2048 = 8 b x 256
    int b = blk >> 8;
    int n = (blk & 255) * 4 + wid;
    const __half* E0 = d_E + ((size_t)(b * 2) * NP + n) * NP;
    const __half* E1 = E0 + (size_t)NP * NP;

    float s0 = 0.f, s1 = 0.f, s2 = 0.f;
    #pragma unroll 4
    for (int i = 0; i < 8; i++) {
        int c4 = i * 32 + lane;
        uint2 a0 = ((const uint2*)E0)[c4];
        uint2 b0 = ((const uint2*)E1)[c4];
        float2 p0 = __half22float2(*(__half2*)&a0.x);
        float2 p1 = __half22float2(*(__half2*)&a0.y);
        float2 q0 = __half22float2(*(__half2*)&b0.x);
        float2 q1 = __half22float2(*(__half2*)&b0.y);
        s0 += (p0.x + p0.y) + (p1.x + p1.y);
        s1 += (q0.x + q0.y) + (q1.x + q1.y);
        s2 += (sqrta(p0.x * q0.x) + sqrta(p0.y * q0.y)) +
              (sqrta(p1.x * q1.x) + sqrta(p1.y * q1.y));
    }
    #pragma unroll
    for (int off = 16; off; off >>= 1) {
        s0 += __shfl_xor_sync(0xffffffffu, s0, off);
        s1 += __shfl_xor_sync(0xffffffffu, s1, off);
        s2 += __shfl_xor_sync(0xffffffffu, s2, off);
    }
    if (lane < 3) {
        float v = (lane == 0) ? s0 : (lane == 1) ? s1 : s2;
        float w = (lane == 2) ? (1.0f / v) : rsqrta(v);
        d_w[(b * 3 + lane) * NP + n] = w;
    }
}

// ---- branch-free sorted top-3 insert (t0 >= t1 >= t2, all values > 0) ----
__device__ __forceinline__ void ins3(float v, float& t0, float& t1, float& t2) {
    float lo0 = fminf(v, t0);
    t0 = fmaxf(v, t0);
    float lo1 = fminf(lo0, t1);
    t1 = fmaxf(lo0, t1);
    t2 = fmaxf(lo1, t2);
}
__device__ __forceinline__ void merge3(float& a0, float& a1, float& a2,
                                       float b0, float b1, float b2) {
    float mx0 = fmaxf(a0, b0), mn0 = fminf(a0, b0);
    float mx1 = fmaxf(a1, b1);
    float mx2 = fmaxf(a2, b2);
    a0 = mx0;
    a1 = fmaxf(mn0, mx1);
    a2 = fmaxf(fminf(mn0, mx1), mx2);
}

// ================= K4: top-3 per row on monotone keys (fp16 E); 1 row/warp ==
// keys: ch0 = E0*w0[m], ch1 = E1*w1[m], ch2 = E0*E1*i2[m];
// final (monotone) transform applied post-selection.
__global__ void __launch_bounds__(128) k4_final(float* __restrict__ out) {
    __shared__ __align__(16) float ws[3][NP];   // w0, w1, i2
    int tid = threadIdx.x, wid = tid >> 5, lane = tid & 31;
    int blk = blockIdx.x;            // 2048 = 8 b x 256
    int b = blk >> 8;
    for (int idx = tid; idx < 3 * NP / 4; idx += 128)
        ((float4*)ws)[idx] = *((const float4*)(d_w + b * 3 * NP) + idx);
    __syncthreads();

    int n = (blk & 255) * 4 + wid;
    const __half* E0 = d_E + ((size_t)(b * 2) * NP + n) * NP;
    const __half* E1 = E0 + (size_t)NP * NP;

    float t[9];
    #pragma unroll
    for (int j = 0; j < 9; j++) t[j] = 0.f;

    #pragma unroll 4
    for (int i = 0; i < 8; i++) {
        int c4 = i * 32 + lane;                 // quad of 4 halfs / 4 m
        uint2 a0 = ((const uint2*)E0)[c4];
        uint2 b0 = ((const uint2*)E1)[c4];
        float4 w0 = ((const float4*)ws[0])[c4];
        float4 w1 = ((const float4*)ws[1])[c4];
        float4 i2 = ((const float4*)ws[2])[c4];
        float2 e0a = __half22float2(*(__half2*)&a0.x);
        float2 e0b = __half22float2(*(__half2*)&a0.y);
        float2 e1a = __half22float2(*(__half2*)&b0.x);
        float2 e1b = __half22float2(*(__half2*)&b0.y);
        ins3(e0a.x * w0.x, t[0], t[1], t[2]);
        ins3(e0a.y * w0.y, t[0], t[1], t[2]);
        ins3(e0b.x * w0.z, t[0], t[1], t[2]);
        ins3(e0b.y * w0.w, t[0], t[1], t[2]);
        ins3(e1a.x * w1.x, t[3], t[4], t[5]);
        ins3(e1a.y * w1.y, t[3], t[4], t[5]);
        ins3(e1b.x * w1.z, t[3], t[4], t[5]);
        ins3(e1b.y * w1.w, t[3], t[4], t[5]);
        ins3(e0a.x * e1a.x * i2.x, t[6], t[7], t[8]);
        ins3(e0a.y * e1a.y * i2.y, t[6], t[7], t[8]);
        ins3(e0b.x * e1b.x * i2.z, t[6], t[7], t[8]);
        ins3(e0b.y * e1b.y * i2.w, t[6], t[7], t[8]);
    }
    // butterfly merge: all lanes end with identical top-3 per channel
    #pragma unroll
    for (int off = 16; off; off >>= 1) {
        #pragma unroll
        for (int c = 0; c < 3; c++) {
            float b0 = __shfl_xor_sync(0xffffffffu, t[c * 3], off);
            float b1 = __shfl_xor_sync(0xffffffffu, t[c * 3 + 1], off);
            float b2 = __shfl_xor_sync(0xffffffffu, t[c * 3 + 2], off);
            merge3(t[c * 3], t[c * 3 + 1], t[c * 3 + 2], b0, b1, b2);
        }
    }
    // scatter: lanes 0..11 write (k, pix)
    if (lane < 12) {
        int k = lane >> 2, pix = lane & 3;
        int chn = (pix == 0) ? 0 : ((pix == 3) ? 1 : 2);
        float a0 = (chn == 0) ? t[0] : (chn == 1) ? t[3] : t[6];
        float a1 = (chn == 0) ? t[1] : (chn == 1) ? t[4] : t[7];
        float a2 = (chn == 0) ? t[2] : (chn == 1) ? t[5] : t[8];
        float key = (k == 0) ? a0 : (k == 1) ? a1 : a2;
        float wn = ws[chn][n];
        float val;
        if (chn == 2) val = key * wn;
        else { float q = key * wn; val = q * q; }
        int rn = n >> 5, cn = n & 31;
        int hh = 2 * rn + (pix >> 1), ww = 2 * cn + (pix & 1);
        out[(((size_t)b * 3 + k) * HH + hh) * WW + ww] = val;
    }
}

// ================= launch ====================================================
extern "C" void kernel_launch(void* const* d_in, const int* in_sizes, int n_in,
                              void* d_out, int out_size) {
    const float* x = (const float*)d_in[0];
    const float* alpha = (const float*)d_in[1];
    float* out = (float*)d_out;

    cudaFuncSetAttribute(k2_gemm, cudaFuncAttributeMaxDynamicSharedMemorySize,
                         K2_SMEM);

    k1_norm<<<dim3(2 * HH, BB), 128>>>(x);
    k2_gemm<<<dim3(36, 16), 256, K2_SMEM>>>(alpha);
    k3_rowsum<<<2048, 128>>>();
    k4_final<<<2048, 128>>>(out);
}

// round 15
// speedup vs baseline: 1.3299x; 1.3299x over previous
#include <cuda_runtime.h>
#include <cuda_bf16.h>
#include <cuda_fp16.h>
#include <cstdint>
#include <math.h>

#define BB 8
#define CC_ 128
#define HH 64
#define WW 64
#define NPH 32
#define NP 1024

typedef unsigned long long u64;

// ---------------- scratch (device globals; no allocs allowed) ----------------
__device__ __half d_xh[16 * NP * CC_];                  // [z][n][c] fp16, 4 MB
__device__ __half d_E[(size_t)16 * NP * NP];            // [z][n][m] E=exp(a*f) 32 MB
__device__ float d_w[BB * 3 * NP];                      // [b][ch][n]: w0,w1,i2

// ---------------- helpers ----------------
__device__ __forceinline__ uint32_t smem_to_u32(const void* p) {
    uint32_t a;
    asm("{ .reg .u64 t; cvta.to.shared.u64 t, %1; cvt.u32.u64 %0, t; }"
        : "=r"(a) : "l"(p));
    return a;
}
__device__ __forceinline__ float sqrta(float x) {
    float r; asm("sqrt.approx.f32 %0, %1;" : "=f"(r) : "f"(x)); return r;
}
__device__ __forceinline__ float rsqrta(float x) {
    float r; asm("rsqrt.approx.f32 %0, %1;" : "=f"(r) : "f"(x)); return r;
}
#define LDSM_X4(r, addr) \
    asm volatile("ldmatrix.sync.aligned.m8n8.x4.shared.b16 {%0,%1,%2,%3}, [%4];" \
        : "=r"((r)[0]), "=r"((r)[1]), "=r"((r)[2]), "=r"((r)[3]) : "r"(addr))
#define MMA16816F16(c, a, b) \
    asm volatile("mma.sync.aligned.m16n8k16.row.col.f32.f16.f16.f32 " \
        "{%0,%1,%2,%3}, {%4,%5,%6,%7}, {%8,%9}, {%0,%1,%2,%3};" \
        : "+f"((c)[0]), "+f"((c)[1]), "+f"((c)[2]), "+f"((c)[3]) \
        : "r"((a)[0]), "r"((a)[1]), "r"((a)[2]), "r"((a)[3]), \
          "r"((b)[0]), "r"((b)[1]))

// swizzled smem byte offset for fp16 tile [128 rows][16 x 16B chunks] (256B rows)
__device__ __forceinline__ uint32_t sw_off(int row, int c16) {
    return (uint32_t)((((row << 1) + (c16 >> 3)) << 7) |
                      ((((c16 & 7) ^ (row & 7))) << 4));
}

// ================= K1: L2-normalize over C, extract diag pixels -> fp16 =====
// block = (b, h, w-half): 128c x 32w tile; writes 16 patch columns (one plane).
__global__ void __launch_bounds__(128) k1_norm(const float* __restrict__ x) {
    __shared__ float xs[CC_][33];
    __shared__ float ssp[4][32];
    __shared__ float invn[32];
    int b = blockIdx.y;
    int hw = blockIdx.x;                 // 0..127
    int h = hw >> 1, half = hw & 1;
    int tid = threadIdx.x;
    const float* xrow = x + ((size_t)b * CC_ * HH + h) * WW + half * 32;
    for (int idx = tid; idx < CC_ * 32; idx += 128) {
        int c = idx >> 5, w = idx & 31;
        xs[c][w] = xrow[(size_t)c * HH * WW + w];
    }
    __syncthreads();
    {
        int w = tid & 31, c4 = tid >> 5;
        float ss = 0.f;
        #pragma unroll 8
        for (int c = c4 * 32; c < c4 * 32 + 32; c++) {
            float v = xs[c][w];
            ss += v * v;
        }
        ssp[c4][w] = ss;
    }
    __syncthreads();
    if (tid < 32) {
        float s = ssp[0][tid] + ssp[1][tid] + ssp[2][tid] + ssp[3][tid];
        invn[tid] = 1.0f / fmaxf(sqrtf(s), 1e-12f);
    }
    __syncthreads();
    int p = h & 1;
    int z = b * 2 + p;
    int nb = (h >> 1) * NPH + half * 16;
    for (int idx = tid; idx < 16 * CC_; idx += 128) {
        int j16 = idx >> 7, c = idx & 127;
        int wl = 2 * j16 + p;            // local w within the 32-col window
        float v = xs[c][wl] * invn[wl];
        size_t o = ((size_t)z * NP + nb + j16) * CC_ + c;
        d_xh[o] = __float2half(v);
    }
}

// ================= K2: single-term fp16 Gram GEMM + fused exp(mask) =========
// E[z][n][m] = exp(corr * alpha*(1-mask)); triangle tiles, fp16 store (norm+T).
// Single fp16 pass: corr rms error ~1.3e-5 (unit-norm columns), negligible vs
// the fp16 E storage error.
#define OP_A 0
#define OP_B 32768
#define STG_LD 129
#define ER_OFF 66048
#define K2_SMEM 66304

__global__ void __launch_bounds__(256, 2) k2_gemm(const float* __restrict__ alphap) {
    extern __shared__ char sm[];
    uint32_t smem_base = smem_to_u32(sm);
    int tid = threadIdx.x;
    int wid = tid >> 5, lane = tid & 31;
    int wm = wid & 3, wn = wid >> 2;
    float* er = (float*)(sm + ER_OFF);
    if (tid < 32) er[tid] = expf(-(float)(tid * tid) / 5.12f);

    // triangle tile decode
    int u = blockIdx.x, ti = 0;
    for (;;) { int row = 8 - ti; if (u < row) break; u -= row; ti++; }
    int tj = ti + u;
    int n0 = ti * 128, m0 = tj * 128;
    int z = blockIdx.y;

    const __half* xh = d_xh + (size_t)z * NP * CC_;

    // load both full-K operand tiles [128 x 128] fp16 (32 KB each)
    for (int idx = tid; idx < 128 * 16; idx += 256) {
        int row = idx >> 4, c16 = idx & 15;
        uint32_t off = sw_off(row, c16);
        size_t ga = (size_t)(n0 + row) * CC_ + c16 * 8;
        size_t gb = (size_t)(m0 + row) * CC_ + c16 * 8;
        *(uint4*)(sm + OP_A + off) = *(const uint4*)(xh + ga);
        *(uint4*)(sm + OP_B + off) = *(const uint4*)(xh + gb);
    }
    __syncthreads();

    float acc[2][8][4];
    #pragma unroll
    for (int i = 0; i < 2; i++)
        #pragma unroll
        for (int j = 0; j < 8; j++)
            #pragma unroll
            for (int q = 0; q < 4; q++) acc[i][j][q] = 0.f;

    int a_row_lo = (lane & 15), a_half = lane >> 4;
    int b_row_lo = (lane & 7) + ((lane >> 4) << 3);
    int b_half = (lane >> 3) & 1;

    uint32_t abase = smem_base + OP_A;
    uint32_t bbase = smem_base + OP_B;
    #pragma unroll
    for (int kc = 0; kc < 8; kc++) {
        uint32_t a[2][4];
        #pragma unroll
        for (int mi = 0; mi < 2; mi++) {
            int row = wm * 32 + mi * 16 + a_row_lo;
            LDSM_X4(a[mi], abase + sw_off(row, 2 * kc + a_half));
        }
        uint32_t bf[4][4];
        #pragma unroll
        for (int ni16 = 0; ni16 < 4; ni16++) {
            int row = wn * 64 + ni16 * 16 + b_row_lo;
            LDSM_X4(bf[ni16], bbase + sw_off(row, 2 * kc + b_half));
        }
        #pragma unroll
        for (int mi = 0; mi < 2; mi++)
            #pragma unroll
            for (int ni = 0; ni < 8; ni++)
                MMA16816F16(acc[mi][ni], a[mi], (&bf[ni >> 1][(ni & 1) * 2]));
    }
    __syncthreads();   // operands dead; reuse smem as fp32 stage

    // epilogue: E = exp(v * alpha*(1-mask)) into fp32 stage (LD=129)
    float alpha = __ldg(alphap);
    float* stage = (float*)sm;
    int r_base = wm * 32 + (lane >> 2);
    int c_base = wn * 64 + 2 * (lane & 3);
    #pragma unroll
    for (int mi = 0; mi < 2; mi++)
        #pragma unroll
        for (int ni = 0; ni < 8; ni++)
            #pragma unroll
            for (int q = 0; q < 4; q++) {
                int r = r_base + mi * 16 + (q >> 1) * 8;
                int c = c_base + ni * 8 + (q & 1);
                int n = n0 + r, m = m0 + c;
                float g = er[abs((n >> 5) - (m >> 5))] * er[abs((n & 31) - (m & 31))];
                stage[r * STG_LD + c] = __expf(acc[mi][ni][q] * (alpha * (1.0f - g)));
            }
    __syncthreads();

    __half* Ez = d_E + (size_t)z * NP * NP;
    // normal store (half2)
    for (int idx = tid; idx < 128 * 64; idx += 256) {
        int row = idx >> 6, c2 = (idx & 63) * 2;
        float a = stage[row * STG_LD + c2];
        float c = stage[row * STG_LD + c2 + 1];
        __half2 h = __floats2half2_rn(a, c);
        *(__half2*)(Ez + (size_t)(n0 + row) * NP + m0 + c2) = h;
    }
    // transposed store for off-diagonal tiles (half2)
    if (ti != tj) {
        for (int idx = tid; idx < 128 * 64; idx += 256) {
            int mrow = idx >> 6, nc = (idx & 63) * 2;
            float a = stage[nc * STG_LD + mrow];
            float c = stage[(nc + 1) * STG_LD + mrow];
            __half2 h = __floats2half2_rn(a, c);
            *(__half2*)(Ez + (size_t)(m0 + mrow) * NP + n0 + nc) = h;
        }
    }
}

// ================= K3: row sums of E (fp16); 1 warp = 1 row; store w0,w1,i2 =
__global__ void __launch_bounds__(128) k3_rowsum() {
    int tid = threadIdx.x, wid = tid >> 5, lane = tid & 31;
    int blk = blockIdx.x;            // 2048 = 8 b x 256
    int b = blk >> 8;
    int n = (blk & 255) * 4 + wid;
    const __half* E0 = d_E + ((size_t)(b * 2) * NP + n) * NP;
    const __half* E1 = E0 + (size_t)NP * NP;

    float s0 = 0.f, s1 = 0.f, s2 = 0.f;
    #pragma unroll 4
    for (int i = 0; i < 8; i++) {
        int c4 = i * 32 + lane;
        uint2 a0 = ((const uint2*)E0)[c4];
        uint2 b0 = ((const uint2*)E1)[c4];
        float2 p0 = __half22float2(*(__half2*)&a0.x);
        float2 p1 = __half22float2(*(__half2*)&a0.y);
        float2 q0 = __half22float2(*(__half2*)&b0.x);
        float2 q1 = __half22float2(*(__half2*)&b0.y);
        s0 += (p0.x + p0.y) + (p1.x + p1.y);
        s1 += (q0.x + q0.y) + (q1.x + q1.y);
        s2 += (sqrta(p0.x * q0.x) + sqrta(p0.y * q0.y)) +
              (sqrta(p1.x * q1.x) + sqrta(p1.y * q1.y));
    }
    #pragma unroll
    for (int off = 16; off; off >>= 1) {
        s0 += __shfl_xor_sync(0xffffffffu, s0, off);
        s1 += __shfl_xor_sync(0xffffffffu, s1, off);
        s2 += __shfl_xor_sync(0xffffffffu, s2, off);
    }
    if (lane < 3) {
        float v = (lane == 0) ? s0 : (lane == 1) ? s1 : s2;
        float w = (lane == 2) ? (1.0f / v) : rsqrta(v);
        d_w[(b * 3 + lane) * NP + n] = w;
    }
}

// ---- branch-free sorted top-3 insert (t0 >= t1 >= t2, all values > 0) ----
__device__ __forceinline__ void ins3(float v, float& t0, float& t1, float& t2) {
    float lo0 = fminf(v, t0);
    t0 = fmaxf(v, t0);
    float lo1 = fminf(lo0, t1);
    t1 = fmaxf(lo0, t1);
    t2 = fmaxf(lo1, t2);
}
__device__ __forceinline__ void merge3(float& a0, float& a1, float& a2,
                                       float b0, float b1, float b2) {
    float mx0 = fmaxf(a0, b0), mn0 = fminf(a0, b0);
    float mx1 = fmaxf(a1, b1);
    float mx2 = fmaxf(a2, b2);
    a0 = mx0;
    a1 = fmaxf(mn0, mx1);
    a2 = fmaxf(fminf(mn0, mx1), mx2);
}

// ================= K4: top-3 per row on monotone keys (fp16 E); 1 row/warp ==
// keys: ch0 = E0*w0[m], ch1 = E1*w1[m], ch2 = E0*E1*i2[m];
// final (monotone) transform applied post-selection.
__global__ void __launch_bounds__(128) k4_final(float* __restrict__ out) {
    __shared__ __align__(16) float ws[3][NP];   // w0, w1, i2
    int tid = threadIdx.x, wid = tid >> 5, lane = tid & 31;
    int blk = blockIdx.x;            // 2048 = 8 b x 256
    int b = blk >> 8;
    for (int idx = tid; idx < 3 * NP / 4; idx += 128)
        ((float4*)ws)[idx] = *((const float4*)(d_w + b * 3 * NP) + idx);
    __syncthreads();

    int n = (blk & 255) * 4 + wid;
    const __half* E0 = d_E + ((size_t)(b * 2) * NP + n) * NP;
    const __half* E1 = E0 + (size_t)NP * NP;

    float t[9];
    #pragma unroll
    for (int j = 0; j < 9; j++) t[j] = 0.f;

    #pragma unroll 4
    for (int i = 0; i < 8; i++) {
        int c4 = i * 32 + lane;                 // quad of 4 halfs / 4 m
        uint2 a0 = ((const uint2*)E0)[c4];
        uint2 b0 = ((const uint2*)E1)[c4];
        float4 w0 = ((const float4*)ws[0])[c4];
        float4 w1 = ((const float4*)ws[1])[c4];
        float4 i2 = ((const float4*)ws[2])[c4];
        float2 e0a = __half22float2(*(__half2*)&a0.x);
        float2 e0b = __half22float2(*(__half2*)&a0.y);
        float2 e1a = __half22float2(*(__half2*)&b0.x);
        float2 e1b = __half22float2(*(__half2*)&b0.y);
        ins3(e0a.x * w0.x, t[0], t[1], t[2]);
        ins3(e0a.y * w0.y, t[0], t[1], t[2]);
        ins3(e0b.x * w0.z, t[0], t[1], t[2]);
        ins3(e0b.y * w0.w, t[0], t[1], t[2]);
        ins3(e1a.x * w1.x, t[3], t[4], t[5]);
        ins3(e1a.y * w1.y, t[3], t[4], t[5]);
        ins3(e1b.x * w1.z, t[3], t[4], t[5]);
        ins3(e1b.y * w1.w, t[3], t[4], t[5]);
        ins3(e0a.x * e1a.x * i2.x, t[6], t[7], t[8]);
        ins3(e0a.y * e1a.y * i2.y, t[6], t[7], t[8]);
        ins3(e0b.x * e1b.x * i2.z, t[6], t[7], t[8]);
        ins3(e0b.y * e1b.y * i2.w, t[6], t[7], t[8]);
    }
    // butterfly merge: all lanes end with identical top-3 per channel
    #pragma unroll
    for (int off = 16; off; off >>= 1) {
        #pragma unroll
        for (int c = 0; c < 3; c++) {
            float b0 = __shfl_xor_sync(0xffffffffu, t[c * 3], off);
            float b1 = __shfl_xor_sync(0xffffffffu, t[c * 3 + 1], off);
            float b2 = __shfl_xor_sync(0xffffffffu, t[c * 3 + 2], off);
            merge3(t[c * 3], t[c * 3 + 1], t[c * 3 + 2], b0, b1, b2);
        }
    }
    // scatter: lanes 0..11 write (k, pix)
    if (lane < 12) {
        int k = lane >> 2, pix = lane & 3;
        int chn = (pix == 0) ? 0 : ((pix == 3) ? 1 : 2);
        float a0 = (chn == 0) ? t[0] : (chn == 1) ? t[3] : t[6];
        float a1 = (chn == 0) ? t[1] : (chn == 1) ? t[4] : t[7];
        float a2 = (chn == 0) ? t[2] : (chn == 1) ? t[5] : t[8];
        float key = (k == 0) ? a0 : (k == 1) ? a1 : a2;
        float wn = ws[chn][n];
        float val;
        if (chn == 2) val = key * wn;
        else { float q = key * wn; val = q * q; }
        int rn = n >> 5, cn = n & 31;
        int hh = 2 * rn + (pix >> 1), ww = 2 * cn + (pix & 1);
        out[(((size_t)b * 3 + k) * HH + hh) * WW + ww] = val;
    }
}

// ================= launch ====================================================
extern "C" void kernel_launch(void* const* d_in, const int* in_sizes, int n_in,
                              void* d_out, int out_size) {
    const float* x = (const float*)d_in[0];
    const float* alpha = (const float*)d_in[1];
    float* out = (float*)d_out;

    cudaFuncSetAttribute(k2_gemm, cudaFuncAttributeMaxDynamicSharedMemorySize,
                         K2_SMEM);

    k1_norm<<<dim3(2 * HH, BB), 128>>>(x);
    k2_gemm<<<dim3(36, 16), 256, K2_SMEM>>>(alpha);
    k3_rowsum<<<2048, 128>>>();
    k4_final<<<2048, 128>>>(out);
}

// round 16
// speedup vs baseline: 1.3359x; 1.0045x over previous
#include <cuda_runtime.h>
#include <cuda_bf16.h>
#include <cuda_fp16.h>
#include <cstdint>
#include <math.h>

#define BB 8
#define CC_ 128
#define HH 64
#define WW 64
#define NPH 32
#define NP 1024

typedef unsigned long long u64;

// ---------------- scratch (device globals; no allocs allowed) ----------------
__device__ __half d_xh[16 * NP * CC_];                  // [z][n][c] fp16, 4 MB
__device__ __half d_E[(size_t)16 * NP * NP];            // [z][n][m] E=exp(a*f) 32 MB
__device__ float d_w[BB * 3 * NP];                      // [b][ch][n]: w0,w1,i2

// ---------------- helpers ----------------
__device__ __forceinline__ uint32_t smem_to_u32(const void* p) {
    uint32_t a;
    asm("{ .reg .u64 t; cvta.to.shared.u64 t, %1; cvt.u32.u64 %0, t; }"
        : "=r"(a) : "l"(p));
    return a;
}
__device__ __forceinline__ float sqrta(float x) {
    float r; asm("sqrt.approx.f32 %0, %1;" : "=f"(r) : "f"(x)); return r;
}
__device__ __forceinline__ float rsqrta(float x) {
    float r; asm("rsqrt.approx.f32 %0, %1;" : "=f"(r) : "f"(x)); return r;
}
#define LDSM_X4(r, addr) \
    asm volatile("ldmatrix.sync.aligned.m8n8.x4.shared.b16 {%0,%1,%2,%3}, [%4];" \
        : "=r"((r)[0]), "=r"((r)[1]), "=r"((r)[2]), "=r"((r)[3]) : "r"(addr))
#define MMA16816F16(c, a, b) \
    asm volatile("mma.sync.aligned.m16n8k16.row.col.f32.f16.f16.f32 " \
        "{%0,%1,%2,%3}, {%4,%5,%6,%7}, {%8,%9}, {%0,%1,%2,%3};" \
        : "+f"((c)[0]), "+f"((c)[1]), "+f"((c)[2]), "+f"((c)[3]) \
        : "r"((a)[0]), "r"((a)[1]), "r"((a)[2]), "r"((a)[3]), \
          "r"((b)[0]), "r"((b)[1]))

// swizzled smem byte offset for fp16 tile [128 rows][16 x 16B chunks] (256B rows)
__device__ __forceinline__ uint32_t sw_off(int row, int c16) {
    return (uint32_t)((((row << 1) + (c16 >> 3)) << 7) |
                      ((((c16 & 7) ^ (row & 7))) << 4));
}

// ================= K1: L2-normalize over C, extract diag pixels -> fp16 =====
// block = (b, h, w-half): 128c x 32w tile; writes 16 patch columns (one plane).
__global__ void __launch_bounds__(128) k1_norm(const float* __restrict__ x) {
    __shared__ float xs[CC_][33];
    __shared__ float ssp[4][32];
    __shared__ float invn[32];
    int b = blockIdx.y;
    int hw = blockIdx.x;                 // 0..127
    int h = hw >> 1, half = hw & 1;
    int tid = threadIdx.x;
    const float* xrow = x + ((size_t)b * CC_ * HH + h) * WW + half * 32;
    for (int idx = tid; idx < CC_ * 32; idx += 128) {
        int c = idx >> 5, w = idx & 31;
        xs[c][w] = xrow[(size_t)c * HH * WW + w];
    }
    __syncthreads();
    {
        int w = tid & 31, c4 = tid >> 5;
        float ss = 0.f;
        #pragma unroll 8
        for (int c = c4 * 32; c < c4 * 32 + 32; c++) {
            float v = xs[c][w];
            ss += v * v;
        }
        ssp[c4][w] = ss;
    }
    __syncthreads();
    if (tid < 32) {
        float s = ssp[0][tid] + ssp[1][tid] + ssp[2][tid] + ssp[3][tid];
        invn[tid] = 1.0f / fmaxf(sqrtf(s), 1e-12f);
    }
    __syncthreads();
    int p = h & 1;
    int z = b * 2 + p;
    int nb = (h >> 1) * NPH + half * 16;
    for (int idx = tid; idx < 16 * CC_; idx += 128) {
        int j16 = idx >> 7, c = idx & 127;
        int wl = 2 * j16 + p;            // local w within the 32-col window
        float v = xs[c][wl] * invn[wl];
        size_t o = ((size_t)z * NP + nb + j16) * CC_ + c;
        d_xh[o] = __float2half(v);
    }
}

// ================= K2: single-term fp16 Gram GEMM + fused exp(mask) =========
// E[z][n][m] = exp(corr * alpha*(1-mask)); triangle tiles, fp16 store (norm+T).
#define OP_A 0
#define OP_B 32768
#define STG_LD 129
#define ER_OFF 66048
#define K2_SMEM 66304

__global__ void __launch_bounds__(256, 2) k2_gemm(const float* __restrict__ alphap) {
    extern __shared__ char sm[];
    uint32_t smem_base = smem_to_u32(sm);
    int tid = threadIdx.x;
    int wid = tid >> 5, lane = tid & 31;
    int wm = wid & 3, wn = wid >> 2;
    float* er = (float*)(sm + ER_OFF);
    if (tid < 32) er[tid] = expf(-(float)(tid * tid) / 5.12f);

    // triangle tile decode
    int u = blockIdx.x, ti = 0;
    for (;;) { int row = 8 - ti; if (u < row) break; u -= row; ti++; }
    int tj = ti + u;
    int n0 = ti * 128, m0 = tj * 128;
    int z = blockIdx.y;

    const __half* xh = d_xh + (size_t)z * NP * CC_;

    // load both full-K operand tiles [128 x 128] fp16 (32 KB each)
    for (int idx = tid; idx < 128 * 16; idx += 256) {
        int row = idx >> 4, c16 = idx & 15;
        uint32_t off = sw_off(row, c16);
        size_t ga = (size_t)(n0 + row) * CC_ + c16 * 8;
        size_t gb = (size_t)(m0 + row) * CC_ + c16 * 8;
        *(uint4*)(sm + OP_A + off) = *(const uint4*)(xh + ga);
        *(uint4*)(sm + OP_B + off) = *(const uint4*)(xh + gb);
    }
    __syncthreads();

    float acc[2][8][4];
    #pragma unroll
    for (int i = 0; i < 2; i++)
        #pragma unroll
        for (int j = 0; j < 8; j++)
            #pragma unroll
            for (int q = 0; q < 4; q++) acc[i][j][q] = 0.f;

    int a_row_lo = (lane & 15), a_half = lane >> 4;
    int b_row_lo = (lane & 7) + ((lane >> 4) << 3);
    int b_half = (lane >> 3) & 1;

    uint32_t abase = smem_base + OP_A;
    uint32_t bbase = smem_base + OP_B;
    #pragma unroll
    for (int kc = 0; kc < 8; kc++) {
        uint32_t a[2][4];
        #pragma unroll
        for (int mi = 0; mi < 2; mi++) {
            int row = wm * 32 + mi * 16 + a_row_lo;
            LDSM_X4(a[mi], abase + sw_off(row, 2 * kc + a_half));
        }
        uint32_t bf[4][4];
        #pragma unroll
        for (int ni16 = 0; ni16 < 4; ni16++) {
            int row = wn * 64 + ni16 * 16 + b_row_lo;
            LDSM_X4(bf[ni16], bbase + sw_off(row, 2 * kc + b_half));
        }
        #pragma unroll
        for (int mi = 0; mi < 2; mi++)
            #pragma unroll
            for (int ni = 0; ni < 8; ni++)
                MMA16816F16(acc[mi][ni], a[mi], (&bf[ni >> 1][(ni & 1) * 2]));
    }
    __syncthreads();   // operands dead; reuse smem as fp32 stage

    // epilogue: E = exp(v * alpha*(1-mask)) into fp32 stage (LD=129)
    float alpha = __ldg(alphap);
    float* stage = (float*)sm;
    int r_base = wm * 32 + (lane >> 2);
    int c_base = wn * 64 + 2 * (lane & 3);
    #pragma unroll
    for (int mi = 0; mi < 2; mi++)
        #pragma unroll
        for (int ni = 0; ni < 8; ni++)
            #pragma unroll
            for (int q = 0; q < 4; q++) {
                int r = r_base + mi * 16 + (q >> 1) * 8;
                int c = c_base + ni * 8 + (q & 1);
                int n = n0 + r, m = m0 + c;
                float g = er[abs((n >> 5) - (m >> 5))] * er[abs((n & 31) - (m & 31))];
                stage[r * STG_LD + c] = __expf(acc[mi][ni][q] * (alpha * (1.0f - g)));
            }
    __syncthreads();

    __half* Ez = d_E + (size_t)z * NP * NP;
    // normal store (half2)
    for (int idx = tid; idx < 128 * 64; idx += 256) {
        int row = idx >> 6, c2 = (idx & 63) * 2;
        float a = stage[row * STG_LD + c2];
        float c = stage[row * STG_LD + c2 + 1];
        __half2 h = __floats2half2_rn(a, c);
        *(__half2*)(Ez + (size_t)(n0 + row) * NP + m0 + c2) = h;
    }
    // transposed store for off-diagonal tiles (half2)
    if (ti != tj) {
        for (int idx = tid; idx < 128 * 64; idx += 256) {
            int mrow = idx >> 6, nc = (idx & 63) * 2;
            float a = stage[nc * STG_LD + mrow];
            float c = stage[(nc + 1) * STG_LD + mrow];
            __half2 h = __floats2half2_rn(a, c);
            *(__half2*)(Ez + (size_t)(m0 + mrow) * NP + n0 + nc) = h;
        }
    }
}

// ================= K3: row sums of E (fp16); 1 warp = 1 row; store w0,w1,i2 =
__global__ void __launch_bounds__(128) k3_rowsum() {
    int tid = threadIdx.x, wid = tid >> 5, lane = tid & 31;
    int blk = blockIdx.x;            // 2048 = 8 b x 256
    int b = blk >> 8;
    int n = (blk & 255) * 4 + wid;
    const __half* E0 = d_E + ((size_t)(b * 2) * NP + n) * NP;
    const __half* E1 = E0 + (size_t)NP * NP;

    float s0 = 0.f, s1 = 0.f, s2 = 0.f;
    #pragma unroll 4
    for (int i = 0; i < 8; i++) {
        int c4 = i * 32 + lane;
        uint2 a0 = ((const uint2*)E0)[c4];
        uint2 b0 = ((const uint2*)E1)[c4];
        float2 p0 = __half22float2(*(__half2*)&a0.x);
        float2 p1 = __half22float2(*(__half2*)&a0.y);
        float2 q0 = __half22float2(*(__half2*)&b0.x);
        float2 q1 = __half22float2(*(__half2*)&b0.y);
        s0 += (p0.x + p0.y) + (p1.x + p1.y);
        s1 += (q0.x + q0.y) + (q1.x + q1.y);
        s2 += (sqrta(p0.x * q0.x) + sqrta(p0.y * q0.y)) +
              (sqrta(p1.x * q1.x) + sqrta(p1.y * q1.y));
    }
    #pragma unroll
    for (int off = 16; off; off >>= 1) {
        s0 += __shfl_xor_sync(0xffffffffu, s0, off);
        s1 += __shfl_xor_sync(0xffffffffu, s1, off);
        s2 += __shfl_xor_sync(0xffffffffu, s2, off);
    }
    if (lane < 3) {
        float v = (lane == 0) ? s0 : (lane == 1) ? s1 : s2;
        float w = (lane == 2) ? (1.0f / v) : rsqrta(v);
        d_w[(b * 3 + lane) * NP + n] = w;
    }
}

// ---- branch-free sorted top-3 insert (t0 >= t1 >= t2, all values > 0) ----
__device__ __forceinline__ void ins3(float v, float& t0, float& t1, float& t2) {
    float lo0 = fminf(v, t0);
    t0 = fmaxf(v, t0);
    float lo1 = fminf(lo0, t1);
    t1 = fmaxf(lo0, t1);
    t2 = fmaxf(lo1, t2);
}
__device__ __forceinline__ void merge3(float& a0, float& a1, float& a2,
                                       float b0, float b1, float b2) {
    float mx0 = fmaxf(a0, b0), mn0 = fminf(a0, b0);
    float mx1 = fmaxf(a1, b1);
    float mx2 = fmaxf(a2, b2);
    a0 = mx0;
    a1 = fmaxf(mn0, mx1);
    a2 = fmaxf(fminf(mn0, mx1), mx2);
}

// ================= K4: top-3 per row on monotone keys (fp16 E); 2 rows/warp =
// keys: ch0 = E0*w0[m], ch1 = E1*w1[m], ch2 = E0*E1*i2[m];
// final (monotone) transform applied post-selection.
// No smem w cache: w via __ldg (L1-hot, 12 KB/batch); E via __ldcs (last
// reader, evict-first keeps w resident).
__global__ void __launch_bounds__(256) k4_final(float* __restrict__ out) {
    int tid = threadIdx.x, wid = tid >> 5, lane = tid & 31;
    int blk = blockIdx.x;            // 512 = 8 b x 64
    int b = blk >> 6;

    int nb = (blk & 63) * 16 + wid * 2;
    const __half* E0 = d_E + ((size_t)(b * 2) * NP + nb) * NP;
    const __half* E1 = E0 + (size_t)NP * NP;
    const float4* w0p = (const float4*)(d_w + (b * 3 + 0) * NP);
    const float4* w1p = (const float4*)(d_w + (b * 3 + 1) * NP);
    const float4* i2p = (const float4*)(d_w + (b * 3 + 2) * NP);

    float t[18];
    #pragma unroll
    for (int j = 0; j < 18; j++) t[j] = 0.f;

    #pragma unroll 4
    for (int i = 0; i < 8; i++) {
        int c4 = i * 32 + lane;                 // quad of 4 halfs / 4 m
        uint2 a0 = __ldcs((const uint2*)E0 + c4);
        uint2 a1 = __ldcs((const uint2*)(E0 + NP) + c4);
        uint2 b0 = __ldcs((const uint2*)E1 + c4);
        uint2 b1 = __ldcs((const uint2*)(E1 + NP) + c4);
        float4 w0 = __ldg(w0p + c4);
        float4 w1 = __ldg(w1p + c4);
        float4 i2 = __ldg(i2p + c4);
        float2 e00a = __half22float2(*(__half2*)&a0.x);
        float2 e00b = __half22float2(*(__half2*)&a0.y);
        float2 e10a = __half22float2(*(__half2*)&b0.x);
        float2 e10b = __half22float2(*(__half2*)&b0.y);
        // row 0: chains t[0..8]
        ins3(e00a.x * w0.x, t[0], t[1], t[2]);
        ins3(e00a.y * w0.y, t[0], t[1], t[2]);
        ins3(e00b.x * w0.z, t[0], t[1], t[2]);
        ins3(e00b.y * w0.w, t[0], t[1], t[2]);
        ins3(e10a.x * w1.x, t[3], t[4], t[5]);
        ins3(e10a.y * w1.y, t[3], t[4], t[5]);
        ins3(e10b.x * w1.z, t[3], t[4], t[5]);
        ins3(e10b.y * w1.w, t[3], t[4], t[5]);
        ins3(e00a.x * e10a.x * i2.x, t[6], t[7], t[8]);
        ins3(e00a.y * e10a.y * i2.y, t[6], t[7], t[8]);
        ins3(e00b.x * e10b.x * i2.z, t[6], t[7], t[8]);
        ins3(e00b.y * e10b.y * i2.w, t[6], t[7], t[8]);
        // row 1: chains t[9..17]
        float2 e01a = __half22float2(*(__half2*)&a1.x);
        float2 e01b = __half22float2(*(__half2*)&a1.y);
        float2 e11a = __half22float2(*(__half2*)&b1.x);
        float2 e11b = __half22float2(*(__half2*)&b1.y);
        ins3(e01a.x * w0.x, t[9],  t[10], t[11]);
        ins3(e01a.y * w0.y, t[9],  t[10], t[11]);
        ins3(e01b.x * w0.z, t[9],  t[10], t[11]);
        ins3(e01b.y * w0.w, t[9],  t[10], t[11]);
        ins3(e11a.x * w1.x, t[12], t[13], t[14]);
        ins3(e11a.y * w1.y, t[12], t[13], t[14]);
        ins3(e11b.x * w1.z, t[12], t[13], t[14]);
        ins3(e11b.y * w1.w, t[12], t[13], t[14]);
        ins3(e01a.x * e11a.x * i2.x, t[15], t[16], t[17]);
        ins3(e01a.y * e11a.y * i2.y, t[15], t[16], t[17]);
        ins3(e01b.x * e11b.x * i2.z, t[15], t[16], t[17]);
        ins3(e01b.y * e11b.y * i2.w, t[15], t[16], t[17]);
    }
    // butterfly merge: all lanes end with identical top-3 per (row, channel)
    #pragma unroll
    for (int off = 16; off; off >>= 1) {
        #pragma unroll
        for (int c = 0; c < 6; c++) {
            float b0 = __shfl_xor_sync(0xffffffffu, t[c * 3], off);
            float b1 = __shfl_xor_sync(0xffffffffu, t[c * 3 + 1], off);
            float b2 = __shfl_xor_sync(0xffffffffu, t[c * 3 + 2], off);
            merge3(t[c * 3], t[c * 3 + 1], t[c * 3 + 2], b0, b1, b2);
        }
    }
    // scatter: per row, lanes 0..11 write (k, pix)
    if (lane < 12) {
        int k = lane >> 2, pix = lane & 3;
        int chn = (pix == 0) ? 0 : ((pix == 3) ? 1 : 2);
        #pragma unroll
        for (int r = 0; r < 2; r++) {
            const float* tr = t + r * 9;
            float a0 = (chn == 0) ? tr[0] : (chn == 1) ? tr[3] : tr[6];
            float a1 = (chn == 0) ? tr[1] : (chn == 1) ? tr[4] : tr[7];
            float a2 = (chn == 0) ? tr[2] : (chn == 1) ? tr[5] : tr[8];
            float key = (k == 0) ? a0 : (k == 1) ? a1 : a2;
            int n = nb + r;
            float wn = __ldg(&d_w[(b * 3 + chn) * NP + n]);
            float val;
            if (chn == 2) val = key * wn;
            else { float q = key * wn; val = q * q; }
            int rn = n >> 5, cn = n & 31;
            int hh = 2 * rn + (pix >> 1), ww = 2 * cn + (pix & 1);
            out[(((size_t)b * 3 + k) * HH + hh) * WW + ww] = val;
        }
    }
}

// ================= launch ====================================================
extern "C" void kernel_launch(void* const* d_in, const int* in_sizes, int n_in,
                              void* d_out, int out_size) {
    const float* x = (const float*)d_in[0];
    const float* alpha = (const float*)d_in[1];
    float* out = (float*)d_out;

    cudaFuncSetAttribute(k2_gemm, cudaFuncAttributeMaxDynamicSharedMemorySize,
                         K2_SMEM);

    k1_norm<<<dim3(2 * HH, BB), 128>>>(x);
    k2_gemm<<<dim3(36, 16), 256, K2_SMEM>>>(alpha);
    k3_rowsum<<<2048, 128>>>();
    k4_final<<<512, 256>>>(out);
}

// round 17
// speedup vs baseline: 1.3934x; 1.0430x over previous
#include <cuda_runtime.h>
#include <cuda_bf16.h>
#include <cuda_fp16.h>
#include <cstdint>
#include <math.h>

#define BB 8
#define CC_ 128
#define HH 64
#define WW 64
#define NPH 32
#define NP 1024

typedef unsigned long long u64;

// ---------------- scratch (device globals; no allocs allowed) ----------------
__device__ __half d_xh[16 * NP * CC_];                  // [z][n][c] fp16, 4 MB
__device__ __half d_E[(size_t)16 * NP * NP];            // [z][n][m] E=exp(a*f) 32 MB
__device__ float d_w[BB * 3 * NP];                      // [b][ch][n]: w0,w1,i2

// ---------------- helpers ----------------
__device__ __forceinline__ uint32_t smem_to_u32(const void* p) {
    uint32_t a;
    asm("{ .reg .u64 t; cvta.to.shared.u64 t, %1; cvt.u32.u64 %0, t; }"
        : "=r"(a) : "l"(p));
    return a;
}
__device__ __forceinline__ float sqrta(float x) {
    float r; asm("sqrt.approx.f32 %0, %1;" : "=f"(r) : "f"(x)); return r;
}
__device__ __forceinline__ float rsqrta(float x) {
    float r; asm("rsqrt.approx.f32 %0, %1;" : "=f"(r) : "f"(x)); return r;
}
#define LDSM_X4(r, addr) \
    asm volatile("ldmatrix.sync.aligned.m8n8.x4.shared.b16 {%0,%1,%2,%3}, [%4];" \
        : "=r"((r)[0]), "=r"((r)[1]), "=r"((r)[2]), "=r"((r)[3]) : "r"(addr))
#define MMA16816F16(c, a, b) \
    asm volatile("mma.sync.aligned.m16n8k16.row.col.f32.f16.f16.f32 " \
        "{%0,%1,%2,%3}, {%4,%5,%6,%7}, {%8,%9}, {%0,%1,%2,%3};" \
        : "+f"((c)[0]), "+f"((c)[1]), "+f"((c)[2]), "+f"((c)[3]) \
        : "r"((a)[0]), "r"((a)[1]), "r"((a)[2]), "r"((a)[3]), \
          "r"((b)[0]), "r"((b)[1]))

// swizzled smem byte offset for fp16 tile [128 rows][16 x 16B chunks] (256B rows)
__device__ __forceinline__ uint32_t sw_off(int row, int c16) {
    return (uint32_t)((((row << 1) + (c16 >> 3)) << 7) |
                      ((((c16 & 7) ^ (row & 7))) << 4));
}

// ================= K1: L2-normalize over C, extract diag pixels -> fp16 =====
__global__ void __launch_bounds__(128) k1_norm(const float* __restrict__ x) {
    __shared__ float xs[CC_][33];
    __shared__ float ssp[4][32];
    __shared__ float invn[32];
    int b = blockIdx.y;
    int hw = blockIdx.x;                 // 0..127
    int h = hw >> 1, half = hw & 1;
    int tid = threadIdx.x;
    const float* xrow = x + ((size_t)b * CC_ * HH + h) * WW + half * 32;
    for (int idx = tid; idx < CC_ * 32; idx += 128) {
        int c = idx >> 5, w = idx & 31;
        xs[c][w] = xrow[(size_t)c * HH * WW + w];
    }
    __syncthreads();
    {
        int w = tid & 31, c4 = tid >> 5;
        float ss = 0.f;
        #pragma unroll 8
        for (int c = c4 * 32; c < c4 * 32 + 32; c++) {
            float v = xs[c][w];
            ss += v * v;
        }
        ssp[c4][w] = ss;
    }
    __syncthreads();
    if (tid < 32) {
        float s = ssp[0][tid] + ssp[1][tid] + ssp[2][tid] + ssp[3][tid];
        invn[tid] = 1.0f / fmaxf(sqrtf(s), 1e-12f);
    }
    __syncthreads();
    int p = h & 1;
    int z = b * 2 + p;
    int nb = (h >> 1) * NPH + half * 16;
    for (int idx = tid; idx < 16 * CC_; idx += 128) {
        int j16 = idx >> 7, c = idx & 127;
        int wl = 2 * j16 + p;
        float v = xs[c][wl] * invn[wl];
        size_t o = ((size_t)z * NP + nb + j16) * CC_ + c;
        d_xh[o] = __float2half(v);
    }
}

// ================= K2: single-term fp16 Gram GEMM + fused exp(mask) =========
#define OP_A 0
#define OP_B 32768
#define STG_LD 129
#define ER_OFF 66048
#define K2_SMEM 66304

__global__ void __launch_bounds__(256, 2) k2_gemm(const float* __restrict__ alphap) {
    extern __shared__ char sm[];
    uint32_t smem_base = smem_to_u32(sm);
    int tid = threadIdx.x;
    int wid = tid >> 5, lane = tid & 31;
    int wm = wid & 3, wn = wid >> 2;
    float* er = (float*)(sm + ER_OFF);
    if (tid < 32) er[tid] = expf(-(float)(tid * tid) / 5.12f);

    int u = blockIdx.x, ti = 0;
    for (;;) { int row = 8 - ti; if (u < row) break; u -= row; ti++; }
    int tj = ti + u;
    int n0 = ti * 128, m0 = tj * 128;
    int z = blockIdx.y;

    const __half* xh = d_xh + (size_t)z * NP * CC_;

    for (int idx = tid; idx < 128 * 16; idx += 256) {
        int row = idx >> 4, c16 = idx & 15;
        uint32_t off = sw_off(row, c16);
        size_t ga = (size_t)(n0 + row) * CC_ + c16 * 8;
        size_t gb = (size_t)(m0 + row) * CC_ + c16 * 8;
        *(uint4*)(sm + OP_A + off) = *(const uint4*)(xh + ga);
        *(uint4*)(sm + OP_B + off) = *(const uint4*)(xh + gb);
    }
    __syncthreads();

    float acc[2][8][4];
    #pragma unroll
    for (int i = 0; i < 2; i++)
        #pragma unroll
        for (int j = 0; j < 8; j++)
            #pragma unroll
            for (int q = 0; q < 4; q++) acc[i][j][q] = 0.f;

    int a_row_lo = (lane & 15), a_half = lane >> 4;
    int b_row_lo = (lane & 7) + ((lane >> 4) << 3);
    int b_half = (lane >> 3) & 1;

    uint32_t abase = smem_base + OP_A;
    uint32_t bbase = smem_base + OP_B;
    #pragma unroll
    for (int kc = 0; kc < 8; kc++) {
        uint32_t a[2][4];
        #pragma unroll
        for (int mi = 0; mi < 2; mi++) {
            int row = wm * 32 + mi * 16 + a_row_lo;
            LDSM_X4(a[mi], abase + sw_off(row, 2 * kc + a_half));
        }
        uint32_t bf[4][4];
        #pragma unroll
        for (int ni16 = 0; ni16 < 4; ni16++) {
            int row = wn * 64 + ni16 * 16 + b_row_lo;
            LDSM_X4(bf[ni16], bbase + sw_off(row, 2 * kc + b_half));
        }
        #pragma unroll
        for (int mi = 0; mi < 2; mi++)
            #pragma unroll
            for (int ni = 0; ni < 8; ni++)
                MMA16816F16(acc[mi][ni], a[mi], (&bf[ni >> 1][(ni & 1) * 2]));
    }
    __syncthreads();

    float alpha = __ldg(alphap);
    float* stage = (float*)sm;
    int r_base = wm * 32 + (lane >> 2);
    int c_base = wn * 64 + 2 * (lane & 3);
    #pragma unroll
    for (int mi = 0; mi < 2; mi++)
        #pragma unroll
        for (int ni = 0; ni < 8; ni++)
            #pragma unroll
            for (int q = 0; q < 4; q++) {
                int r = r_base + mi * 16 + (q >> 1) * 8;
                int c = c_base + ni * 8 + (q & 1);
                int n = n0 + r, m = m0 + c;
                float g = er[abs((n >> 5) - (m >> 5))] * er[abs((n & 31) - (m & 31))];
                stage[r * STG_LD + c] = __expf(acc[mi][ni][q] * (alpha * (1.0f - g)));
            }
    __syncthreads();

    __half* Ez = d_E + (size_t)z * NP * NP;
    for (int idx = tid; idx < 128 * 64; idx += 256) {
        int row = idx >> 6, c2 = (idx & 63) * 2;
        __half2 h = __floats2half2_rn(stage[row * STG_LD + c2],
                                      stage[row * STG_LD + c2 + 1]);
        *(__half2*)(Ez + (size_t)(n0 + row) * NP + m0 + c2) = h;
    }
    if (ti != tj) {
        for (int idx = tid; idx < 128 * 64; idx += 256) {
            int mrow = idx >> 6, nc = (idx & 63) * 2;
            __half2 h = __floats2half2_rn(stage[nc * STG_LD + mrow],
                                          stage[(nc + 1) * STG_LD + mrow]);
            *(__half2*)(Ez + (size_t)(m0 + mrow) * NP + n0 + nc) = h;
        }
    }
}

// ================= K3: row sums of E (fp16); 1 warp = 1 row (uint4 loads) ===
__global__ void __launch_bounds__(128) k3_rowsum() {
    int tid = threadIdx.x, wid = tid >> 5, lane = tid & 31;
    int blk = blockIdx.x;            // 2048 = 8 b x 256
    int b = blk >> 8;
    int n = (blk & 255) * 4 + wid;
    const __half* E0 = d_E + ((size_t)(b * 2) * NP + n) * NP;
    const __half* E1 = E0 + (size_t)NP * NP;

    float s0 = 0.f, s1 = 0.f, s2 = 0.f;
    #pragma unroll
    for (int i = 0; i < 4; i++) {
        int c8 = i * 32 + lane;
        uint4 a = ((const uint4*)E0)[c8];
        uint4 bq = ((const uint4*)E1)[c8];
        float2 p0 = __half22float2(*(__half2*)&a.x);
        float2 p1 = __half22float2(*(__half2*)&a.y);
        float2 p2 = __half22float2(*(__half2*)&a.z);
        float2 p3 = __half22float2(*(__half2*)&a.w);
        float2 q0 = __half22float2(*(__half2*)&bq.x);
        float2 q1 = __half22float2(*(__half2*)&bq.y);
        float2 q2 = __half22float2(*(__half2*)&bq.z);
        float2 q3 = __half22float2(*(__half2*)&bq.w);
        s0 += ((p0.x + p0.y) + (p1.x + p1.y)) + ((p2.x + p2.y) + (p3.x + p3.y));
        s1 += ((q0.x + q0.y) + (q1.x + q1.y)) + ((q2.x + q2.y) + (q3.x + q3.y));
        s2 += ((sqrta(p0.x * q0.x) + sqrta(p0.y * q0.y)) +
               (sqrta(p1.x * q1.x) + sqrta(p1.y * q1.y))) +
              ((sqrta(p2.x * q2.x) + sqrta(p2.y * q2.y)) +
               (sqrta(p3.x * q3.x) + sqrta(p3.y * q3.y)));
    }
    #pragma unroll
    for (int off = 16; off; off >>= 1) {
        s0 += __shfl_xor_sync(0xffffffffu, s0, off);
        s1 += __shfl_xor_sync(0xffffffffu, s1, off);
        s2 += __shfl_xor_sync(0xffffffffu, s2, off);
    }
    if (lane < 3) {
        float v = (lane == 0) ? s0 : (lane == 1) ? s1 : s2;
        float w = (lane == 2) ? (1.0f / v) : rsqrta(v);
        d_w[(b * 3 + lane) * NP + n] = w;
    }
}

// ---- exact sorted top-3 of a quad via sorting network (9 min/max ops) ------
// (the 4th-largest of a quad can never be in a top-3, so it is discarded)
__device__ __forceinline__ void quad3(float v0, float v1, float v2, float v3,
                                      float& q0, float& q1, float& q2) {
    float hi1 = fmaxf(v0, v1), lo1 = fminf(v0, v1);
    float hi2 = fmaxf(v2, v3), lo2 = fminf(v2, v3);
    q0 = fmaxf(hi1, hi2);
    float m = fminf(hi1, hi2);
    float h = fmaxf(lo1, lo2);
    q1 = fmaxf(m, h);
    q2 = fminf(m, h);
}
// ---- merge two sorted 3-lists -> top3 of the union (7 ops) ----
__device__ __forceinline__ void merge3(float& a0, float& a1, float& a2,
                                       float b0, float b1, float b2) {
    float mx0 = fmaxf(a0, b0), mn0 = fminf(a0, b0);
    float mx1 = fmaxf(a1, b1);
    float mx2 = fmaxf(a2, b2);
    a0 = mx0;
    a1 = fmaxf(mn0, mx1);
    a2 = fmaxf(fminf(mn0, mx1), mx2);
}

// ================= K4: top-3 per row via quad networks (fp16 E); 1 row/warp =
// keys: ch0 = E0*w0[m], ch1 = E1*w1[m], ch2 = E0*E1*i2[m];
// final (monotone) transform applied post-selection. Exact selection.
__global__ void __launch_bounds__(128) k4_final(float* __restrict__ out) {
    int tid = threadIdx.x, wid = tid >> 5, lane = tid & 31;
    int blk = blockIdx.x;            // 2048 = 8 b x 256
    int b = blk >> 8;

    int n = (blk & 255) * 4 + wid;
    const __half* E0 = d_E + ((size_t)(b * 2) * NP + n) * NP;
    const __half* E1 = E0 + (size_t)NP * NP;
    const float4* w0p = (const float4*)(d_w + (b * 3 + 0) * NP);
    const float4* w1p = (const float4*)(d_w + (b * 3 + 1) * NP);
    const float4* i2p = (const float4*)(d_w + (b * 3 + 2) * NP);

    float t[9];
    #pragma unroll
    for (int j = 0; j < 9; j++) t[j] = 0.f;

    #pragma unroll
    for (int i = 0; i < 4; i++) {
        int c8 = i * 32 + lane;                 // 8 halfs / 8 m per lane-iter
        uint4 a = __ldcs((const uint4*)E0 + c8);
        uint4 bq = __ldcs((const uint4*)E1 + c8);
        float4 w0a = __ldg(w0p + 2 * c8), w0b = __ldg(w0p + 2 * c8 + 1);
        float4 w1a = __ldg(w1p + 2 * c8), w1b = __ldg(w1p + 2 * c8 + 1);
        float4 i2a = __ldg(i2p + 2 * c8), i2b = __ldg(i2p + 2 * c8 + 1);
        float2 e0[4], e1[4];
        e0[0] = __half22float2(*(__half2*)&a.x);
        e0[1] = __half22float2(*(__half2*)&a.y);
        e0[2] = __half22float2(*(__half2*)&a.z);
        e0[3] = __half22float2(*(__half2*)&a.w);
        e1[0] = __half22float2(*(__half2*)&bq.x);
        e1[1] = __half22float2(*(__half2*)&bq.y);
        e1[2] = __half22float2(*(__half2*)&bq.z);
        e1[3] = __half22float2(*(__half2*)&bq.w);
        float q0, q1, q2;
        // ch0: two quad networks + merges
        quad3(e0[0].x * w0a.x, e0[0].y * w0a.y, e0[1].x * w0a.z, e0[1].y * w0a.w,
              q0, q1, q2);
        merge3(t[0], t[1], t[2], q0, q1, q2);
        quad3(e0[2].x * w0b.x, e0[2].y * w0b.y, e0[3].x * w0b.z, e0[3].y * w0b.w,
              q0, q1, q2);
        merge3(t[0], t[1], t[2], q0, q1, q2);
        // ch1
        quad3(e1[0].x * w1a.x, e1[0].y * w1a.y, e1[1].x * w1a.z, e1[1].y * w1a.w,
              q0, q1, q2);
        merge3(t[3], t[4], t[5], q0, q1, q2);
        quad3(e1[2].x * w1b.x, e1[2].y * w1b.y, e1[3].x * w1b.z, e1[3].y * w1b.w,
              q0, q1, q2);
        merge3(t[3], t[4], t[5], q0, q1, q2);
        // ch2
        quad3(e0[0].x * e1[0].x * i2a.x, e0[0].y * e1[0].y * i2a.y,
              e0[1].x * e1[1].x * i2a.z, e0[1].y * e1[1].y * i2a.w,
              q0, q1, q2);
        merge3(t[6], t[7], t[8], q0, q1, q2);
        quad3(e0[2].x * e1[2].x * i2b.x, e0[2].y * e1[2].y * i2b.y,
              e0[3].x * e1[3].x * i2b.z, e0[3].y * e1[3].y * i2b.w,
              q0, q1, q2);
        merge3(t[6], t[7], t[8], q0, q1, q2);
    }
    // butterfly merge: all lanes end with identical top-3 per channel
    #pragma unroll
    for (int off = 16; off; off >>= 1) {
        #pragma unroll
        for (int c = 0; c < 3; c++) {
            float b0 = __shfl_xor_sync(0xffffffffu, t[c * 3], off);
            float b1 = __shfl_xor_sync(0xffffffffu, t[c * 3 + 1], off);
            float b2 = __shfl_xor_sync(0xffffffffu, t[c * 3 + 2], off);
            merge3(t[c * 3], t[c * 3 + 1], t[c * 3 + 2], b0, b1, b2);
        }
    }
    // scatter: lanes 0..11 write (k, pix)
    if (lane < 12) {
        int k = lane >> 2, pix = lane & 3;
        int chn = (pix == 0) ? 0 : ((pix == 3) ? 1 : 2);
        float a0 = (chn == 0) ? t[0] : (chn == 1) ? t[3] : t[6];
        float a1 = (chn == 0) ? t[1] : (chn == 1) ? t[4] : t[7];
        float a2 = (chn == 0) ? t[2] : (chn == 1) ? t[5] : t[8];
        float key = (k == 0) ? a0 : (k == 1) ? a1 : a2;
        float wn = __ldg(&d_w[(b * 3 + chn) * NP + n]);
        float val;
        if (chn == 2) val = key * wn;
        else { float q = key * wn; val = q * q; }
        int rn = n >> 5, cn = n & 31;
        int hh = 2 * rn + (pix >> 1), ww = 2 * cn + (pix & 1);
        out[(((size_t)b * 3 + k) * HH + hh) * WW + ww] = val;
    }
}

// ================= launch ====================================================
extern "C" void kernel_launch(void* const* d_in, const int* in_sizes, int n_in,
                              void* d_out, int out_size) {
    const float* x = (const float*)d_in[0];
    const float* alpha = (const float*)d_in[1];
    float* out = (float*)d_out;

    cudaFuncSetAttribute(k2_gemm, cudaFuncAttributeMaxDynamicSharedMemorySize,
                         K2_SMEM);

    k1_norm<<<dim3(2 * HH, BB), 128>>>(x);
    k2_gemm<<<dim3(36, 16), 256, K2_SMEM>>>(alpha);
    k3_rowsum<<<2048, 128>>>();
    k4_final<<<2048, 128>>>(out);
}